// round 1
// baseline (speedup 1.0000x reference)
#include <cuda_runtime.h>
#include <math.h>

// ---------------------------------------------------------------------------
// CausalSelfAttention: x[2,2048,1024] -> out[2,2048,1024]
//   qkv = x @ w_attn + b_attn        (4096 x 3072, K=1024)
//   rope(q,k), split heads (H=16, HD=64)
//   flash causal attention (scale 1/8)
//   out = y @ w_proj + b_proj        (4096 x 1024, K=1024)
// Round 0: all-fp32 baseline. Tiled SGEMM + fp32 flash attention.
// ---------------------------------------------------------------------------

#define BATCH 2
#define SEQ   2048
#define CH    1024
#define NHEAD 16
#define HDIM  64
#define NROW  (BATCH * SEQ)          // 4096

// scratch (static device arrays; no allocation allowed)
__device__ float d_qkv[NROW * 3 * CH];     // 50.3 MB
__device__ float d_Qh[NROW * CH];          // [bh][t][d]
__device__ float d_Kh[NROW * CH];
__device__ float d_Vh[NROW * CH];
__device__ float d_attn[NROW * CH];        // [b*T+t][C]

// ---------------------------------------------------------------------------
// SGEMM: C[M,N] = A[M,K] @ B[K,N] + bias[N]
// 128x128 tile, BK=8, 256 threads, 8x8 micro-tile per thread.
// ---------------------------------------------------------------------------
__global__ __launch_bounds__(256, 2)
void sgemm_bias(const float* __restrict__ A, const float* __restrict__ B,
                const float* __restrict__ bias, float* __restrict__ C,
                int M, int N, int K)
{
    __shared__ float As[8][128];
    __shared__ float Bs[8][128];

    const int tid = threadIdx.x;
    const int tx  = tid & 15;       // 0..15 -> N
    const int ty  = tid >> 4;       // 0..15 -> M
    const int bx  = blockIdx.x;     // N tile
    const int by  = blockIdx.y;     // M tile

    const int rA   = (tid >> 1);            // 0..127
    const int cA   = (tid & 1) * 4;         // 0 or 4
    const int rB   = tid >> 5;              // 0..7
    const int cB   = (tid & 31) * 4;        // 0..124

    const float* Aptr = A + (by * 128 + rA) * K + cA;
    const float* Bptr = B + rB * N + bx * 128 + cB;

    float acc[8][8];
#pragma unroll
    for (int i = 0; i < 8; i++)
#pragma unroll
        for (int j = 0; j < 8; j++) acc[i][j] = 0.f;

    for (int k0 = 0; k0 < K; k0 += 8) {
        float4 av = *(const float4*)(Aptr + k0);
        float4 bv = *(const float4*)(Bptr + k0 * N);

        As[cA + 0][rA] = av.x;
        As[cA + 1][rA] = av.y;
        As[cA + 2][rA] = av.z;
        As[cA + 3][rA] = av.w;
        *(float4*)&Bs[rB][cB] = bv;
        __syncthreads();

#pragma unroll
        for (int kk = 0; kk < 8; kk++) {
            float a[8], b[8];
            *(float4*)(a)     = *(float4*)&As[kk][ty * 8];
            *(float4*)(a + 4) = *(float4*)&As[kk][ty * 8 + 4];
            *(float4*)(b)     = *(float4*)&Bs[kk][tx * 8];
            *(float4*)(b + 4) = *(float4*)&Bs[kk][tx * 8 + 4];
#pragma unroll
            for (int i = 0; i < 8; i++)
#pragma unroll
                for (int j = 0; j < 8; j++)
                    acc[i][j] += a[i] * b[j];
        }
        __syncthreads();
    }

    const int row0 = by * 128 + ty * 8;
    const int col0 = bx * 128 + tx * 8;
    float4 bia0 = *(const float4*)(bias + col0);
    float4 bia1 = *(const float4*)(bias + col0 + 4);
#pragma unroll
    for (int i = 0; i < 8; i++) {
        float4 v0 = make_float4(acc[i][0] + bia0.x, acc[i][1] + bia0.y,
                                acc[i][2] + bia0.z, acc[i][3] + bia0.w);
        float4 v1 = make_float4(acc[i][4] + bia1.x, acc[i][5] + bia1.y,
                                acc[i][6] + bia1.z, acc[i][7] + bia1.w);
        *(float4*)(C + (size_t)(row0 + i) * N + col0)     = v0;
        *(float4*)(C + (size_t)(row0 + i) * N + col0 + 4) = v1;
    }
}

// ---------------------------------------------------------------------------
// RoPE + head split: qkv[4096,3072] -> Qh/Kh/Vh as [bh][t][d]
// one thread per (row, channel-pair)
// ---------------------------------------------------------------------------
__global__ void rope_split(const float* __restrict__ qkv,
                           const float* __restrict__ cosT,
                           const float* __restrict__ sinT)
{
    int idx = blockIdx.x * blockDim.x + threadIdx.x;   // 4096*512
    if (idx >= NROW * (CH / 2)) return;
    int p = idx & 511;          // pair index within C/2
    int n = idx >> 9;           // row 0..4095
    int t = n & (SEQ - 1);
    int b = n >> 11;
    int h  = p >> 5;            // (p*2)/64
    int pr = p & 31;            // rotary pair within head
    int d0 = pr * 2;

    float c = cosT[t * 32 + pr];
    float s = sinT[t * 32 + pr];

    const float* row = qkv + (size_t)n * (3 * CH);
    float2 q = *(const float2*)(row + p * 2);
    float2 k = *(const float2*)(row + CH + p * 2);
    float2 v = *(const float2*)(row + 2 * CH + p * 2);

    size_t o = ((size_t)(b * NHEAD + h) * SEQ + t) * HDIM + d0;
    float2 qo = make_float2(q.x * c - q.y * s, q.x * s + q.y * c);
    float2 ko = make_float2(k.x * c - k.y * s, k.x * s + k.y * c);
    *(float2*)(d_Qh + o) = qo;
    *(float2*)(d_Kh + o) = ko;
    *(float2*)(d_Vh + o) = v;
}

// ---------------------------------------------------------------------------
// Flash attention, fp32, causal. 64 queries x 64 keys per tile.
// 256 threads = 16x16; each thread owns a 4x4 micro-tile.
// smem: Qs [64][68] (d-major), KP [64][68] (K^T, then reused for P^T),
//       Vs [64][64].
// ---------------------------------------------------------------------------
#define FL_STR 68
#define FL_SMEM_FLOATS (64 * FL_STR * 2 + 64 * 64)
#define FL_SMEM_BYTES  (FL_SMEM_FLOATS * 4)

__global__ __launch_bounds__(256)
void flash_attn(const float* __restrict__ Q, const float* __restrict__ K,
                const float* __restrict__ V, float* __restrict__ Y)
{
    extern __shared__ float sm[];
    float* Qs = sm;                     // [d][q] stride FL_STR
    float* KP = sm + 64 * FL_STR;       // [d][k] then [k][q] stride FL_STR
    float* Vs = sm + 2 * 64 * FL_STR;   // [k][d] stride 64

    const int tid = threadIdx.x;
    const int tx  = tid & 15;
    const int ty  = tid >> 4;
    const int qt  = blockIdx.x;          // 0..31
    const int bh  = blockIdx.y;          // 0..31
    const int q0  = qt * 64;

    const float* Qb = Q + (size_t)bh * SEQ * HDIM;
    const float* Kb = K + (size_t)bh * SEQ * HDIM;
    const float* Vb = V + (size_t)bh * SEQ * HDIM;

    // load Q tile transposed: Qs[d][q]
#pragma unroll
    for (int it = 0; it < 4; it++) {
        int idx = tid + it * 256;        // 0..1023 float4s
        int r   = idx >> 4;              // q row 0..63
        int c4  = (idx & 15) * 4;        // d base
        float4 v = *(const float4*)(Qb + (size_t)(q0 + r) * HDIM + c4);
        Qs[(c4 + 0) * FL_STR + r] = v.x;
        Qs[(c4 + 1) * FL_STR + r] = v.y;
        Qs[(c4 + 2) * FL_STR + r] = v.z;
        Qs[(c4 + 3) * FL_STR + r] = v.w;
    }

    float m_i[4], l_i[4], o[4][4];
#pragma unroll
    for (int i = 0; i < 4; i++) {
        m_i[i] = -INFINITY; l_i[i] = 0.f;
#pragma unroll
        for (int j = 0; j < 4; j++) o[i][j] = 0.f;
    }

    const int ntiles = qt + 1;
    for (int jt = 0; jt < ntiles; jt++) {
        const int j0 = jt * 64;
        __syncthreads();   // protect KP/Vs from previous iteration

        // load K (transposed) and V tiles
#pragma unroll
        for (int it = 0; it < 4; it++) {
            int idx = tid + it * 256;
            int r   = idx >> 4;
            int c4  = (idx & 15) * 4;
            float4 kv = *(const float4*)(Kb + (size_t)(j0 + r) * HDIM + c4);
            KP[(c4 + 0) * FL_STR + r] = kv.x;
            KP[(c4 + 1) * FL_STR + r] = kv.y;
            KP[(c4 + 2) * FL_STR + r] = kv.z;
            KP[(c4 + 3) * FL_STR + r] = kv.w;
            float4 vv = *(const float4*)(Vb + (size_t)(j0 + r) * HDIM + c4);
            *(float4*)&Vs[r * 64 + c4] = vv;
        }
        __syncthreads();

        // S = Q @ K^T  (4x4 per thread)
        float s[4][4];
#pragma unroll
        for (int i = 0; i < 4; i++)
#pragma unroll
            for (int j = 0; j < 4; j++) s[i][j] = 0.f;

#pragma unroll 8
        for (int d = 0; d < 64; d++) {
            float4 a = *(float4*)&Qs[d * FL_STR + ty * 4];
            float4 b = *(float4*)&KP[d * FL_STR + tx * 4];
            float ar[4] = {a.x, a.y, a.z, a.w};
            float br[4] = {b.x, b.y, b.z, b.w};
#pragma unroll
            for (int i = 0; i < 4; i++)
#pragma unroll
                for (int j = 0; j < 4; j++)
                    s[i][j] += ar[i] * br[j];
        }

        const float scale = 0.125f;
#pragma unroll
        for (int i = 0; i < 4; i++)
#pragma unroll
            for (int j = 0; j < 4; j++) s[i][j] *= scale;

        if (jt == qt) {   // diagonal tile: causal mask
#pragma unroll
            for (int i = 0; i < 4; i++) {
                int qi = q0 + ty * 4 + i;
#pragma unroll
                for (int j = 0; j < 4; j++) {
                    int kj = j0 + tx * 4 + j;
                    if (kj > qi) s[i][j] = -INFINITY;
                }
            }
        }

        // online softmax
        float p[4][4];
#pragma unroll
        for (int i = 0; i < 4; i++) {
            float rmax = fmaxf(fmaxf(s[i][0], s[i][1]), fmaxf(s[i][2], s[i][3]));
#pragma unroll
            for (int mks = 1; mks <= 8; mks <<= 1)
                rmax = fmaxf(rmax, __shfl_xor_sync(0xffffffffu, rmax, mks));
            float mnew = fmaxf(m_i[i], rmax);
            float corr = __expf(m_i[i] - mnew);
            float rsum = 0.f;
#pragma unroll
            for (int j = 0; j < 4; j++) {
                p[i][j] = __expf(s[i][j] - mnew);
                rsum += p[i][j];
            }
#pragma unroll
            for (int mks = 1; mks <= 8; mks <<= 1)
                rsum += __shfl_xor_sync(0xffffffffu, rsum, mks);
            l_i[i] = l_i[i] * corr + rsum;
            m_i[i] = mnew;
#pragma unroll
            for (int j = 0; j < 4; j++) o[i][j] *= corr;
        }

        __syncthreads();   // all threads done reading K from KP

        // write P^T into KP: KP[k][q]
#pragma unroll
        for (int j = 0; j < 4; j++) {
            float4 col = make_float4(p[0][j], p[1][j], p[2][j], p[3][j]);
            *(float4*)&KP[(tx * 4 + j) * FL_STR + ty * 4] = col;
        }
        __syncthreads();

        // O += P @ V
#pragma unroll 8
        for (int k = 0; k < 64; k++) {
            float4 a = *(float4*)&KP[k * FL_STR + ty * 4];
            float4 b = *(float4*)&Vs[k * 64 + tx * 4];
            float ar[4] = {a.x, a.y, a.z, a.w};
            float br[4] = {b.x, b.y, b.z, b.w};
#pragma unroll
            for (int i = 0; i < 4; i++)
#pragma unroll
                for (int j = 0; j < 4; j++)
                    o[i][j] += ar[i] * br[j];
        }
    }

    // epilogue: normalize, write to [b*T+t][C] layout
    const int b = bh >> 4;
    const int h = bh & 15;
#pragma unroll
    for (int i = 0; i < 4; i++) {
        float inv = 1.f / l_i[i];
        int qi = q0 + ty * 4 + i;
        float4 v = make_float4(o[i][0] * inv, o[i][1] * inv,
                               o[i][2] * inv, o[i][3] * inv);
        *(float4*)(Y + ((size_t)(b * SEQ + qi)) * CH + h * HDIM + tx * 4) = v;
    }
}

// ---------------------------------------------------------------------------
extern "C" void kernel_launch(void* const* d_in, const int* in_sizes, int n_in,
                              void* d_out, int out_size)
{
    const float* x      = (const float*)d_in[0];
    const float* cosT   = (const float*)d_in[1];
    const float* sinT   = (const float*)d_in[2];
    const float* w_attn = (const float*)d_in[3];
    const float* b_attn = (const float*)d_in[4];
    const float* w_proj = (const float*)d_in[5];
    const float* b_proj = (const float*)d_in[6];
    float* out = (float*)d_out;

    float *qkv, *Qh, *Kh, *Vh, *attn;
    cudaGetSymbolAddress((void**)&qkv,  d_qkv);
    cudaGetSymbolAddress((void**)&Qh,   d_Qh);
    cudaGetSymbolAddress((void**)&Kh,   d_Kh);
    cudaGetSymbolAddress((void**)&Vh,   d_Vh);
    cudaGetSymbolAddress((void**)&attn, d_attn);

    // 1) QKV GEMM: [4096,3072] = x @ w_attn + b_attn
    sgemm_bias<<<dim3(3 * CH / 128, NROW / 128), 256>>>(
        x, w_attn, b_attn, qkv, NROW, 3 * CH, CH);

    // 2) RoPE + split heads
    {
        int total = NROW * (CH / 2);
        rope_split<<<(total + 255) / 256, 256>>>(qkv, cosT, sinT);
    }

    // 3) flash attention
    cudaFuncSetAttribute(flash_attn, cudaFuncAttributeMaxDynamicSharedMemorySize,
                         FL_SMEM_BYTES);
    flash_attn<<<dim3(SEQ / 64, BATCH * NHEAD), 256, FL_SMEM_BYTES>>>(
        Qh, Kh, Vh, attn);

    // 4) projection GEMM: out = attn @ w_proj + b_proj
    sgemm_bias<<<dim3(CH / 128, NROW / 128), 256>>>(
        attn, w_proj, b_proj, out, NROW, CH, CH);
}